// round 2
// baseline (speedup 1.0000x reference)
#include <cuda_runtime.h>
#include <math.h>

#define B_   2
#define HGT  128
#define WID  128
#define C_   128
#define NWIN 64          // 8x8 windows
#define WT   256         // tokens per window (16x16)
#define LTOK (HGT*WID)   // 16384
#define MT   (B_*LTOK)   // 32768
#define HID_ 1024
#define SCALE 0.08838834764831845f  // 1/sqrt(128)

// ---------------- device scratch (static, no allocs) ----------------
static __device__ float g_q [MT*C_];
static __device__ float g_k [MT*C_];
static __device__ float g_v [MT*C_];
static __device__ float g_sc[(size_t)B_*NWIN*WT*WT];   // 32 MB, softmax in place
static __device__ float g_ao[MT*C_];
static __device__ float g_t1[MT*C_];
static __device__ float g_msg[MT*C_];
static __device__ float g_hid[(size_t)MT*HID_];        // 128 MB

// token (window n, slot i) -> base offset into (b,h,w,c) tensor.
// Same map serves gather (shift by -8 on read) and scatter (shift by +8 on write).
__device__ __forceinline__ int tok_off(int b, int n, int i) {
    int wy = n >> 3, wx = n & 7;
    int gh = ((wy << 4) + (i >> 4) + 8) & 127;
    int gw = ((wx << 4) + (i & 15) + 8) & 127;
    return ((b * HGT + gh) * WID + gw) * C_;
}

// ---------------- generic tiled GEMM: C = A(MxK) @ B(KxN) ----------------
__global__ __launch_bounds__(256) void gemm64(
    const float* __restrict__ A, const float* __restrict__ B,
    float* __restrict__ C, int M, int N, int K)
{
    __shared__ float As[16][64];
    __shared__ float Bs[16][64];
    const int bm0 = blockIdx.y * 64, bn0 = blockIdx.x * 64;
    const int tid = threadIdx.x;
    const int tx = tid & 15, ty = tid >> 4;
    float acc[4][4] = {};

    for (int k0 = 0; k0 < K; k0 += 16) {
        #pragma unroll
        for (int l = tid; l < 1024; l += 256) {
            int r = l >> 4, kk = l & 15;
            As[kk][r] = A[(size_t)(bm0 + r) * K + (k0 + kk)];
        }
        #pragma unroll
        for (int l = tid; l < 1024; l += 256) {
            int kk = l >> 6, cn = l & 63;
            Bs[kk][cn] = B[(size_t)(k0 + kk) * N + (bn0 + cn)];
        }
        __syncthreads();
        #pragma unroll
        for (int kk = 0; kk < 16; ++kk) {
            float a[4], bv[4];
            #pragma unroll
            for (int i = 0; i < 4; ++i) a[i]  = As[kk][ty*4 + i];
            #pragma unroll
            for (int j = 0; j < 4; ++j) bv[j] = Bs[kk][tx*4 + j];
            #pragma unroll
            for (int i = 0; i < 4; ++i)
                #pragma unroll
                for (int j = 0; j < 4; ++j)
                    acc[i][j] += a[i] * bv[j];
        }
        __syncthreads();
    }
    #pragma unroll
    for (int i = 0; i < 4; ++i)
        #pragma unroll
        for (int j = 0; j < 4; ++j)
            C[(size_t)(bm0 + ty*4 + i) * N + (bn0 + tx*4 + j)] = acc[i][j];
}

// ---------------- window scores: S = Qw @ Kw^T * scale + mask ----------------
__global__ __launch_bounds__(256) void win_scores(
    const float* __restrict__ q, const float* __restrict__ k,
    const float* __restrict__ mask, float* __restrict__ sc)
{
    const int bw = blockIdx.z;            // 0..127
    const int b = bw >> 6, n = bw & 63;
    const int bi0 = blockIdx.y * 64, bj0 = blockIdx.x * 64;
    const int tid = threadIdx.x;
    const int tx = tid & 15, ty = tid >> 4;

    __shared__ float Qs[16][64], Ks[16][64];
    __shared__ int offQ[64], offK[64];
    if (tid < 64)        offQ[tid]      = tok_off(b, n, bi0 + tid);
    else if (tid < 128)  offK[tid - 64] = tok_off(b, n, bj0 + tid - 64);
    __syncthreads();

    float acc[4][4] = {};
    for (int k0 = 0; k0 < C_; k0 += 16) {
        #pragma unroll
        for (int l = tid; l < 1024; l += 256) {
            int r = l >> 4, kk = l & 15;
            Qs[kk][r] = q[offQ[r] + k0 + kk];
        }
        #pragma unroll
        for (int l = tid; l < 1024; l += 256) {
            int r = l >> 4, kk = l & 15;
            Ks[kk][r] = k[offK[r] + k0 + kk];
        }
        __syncthreads();
        #pragma unroll
        for (int kk = 0; kk < 16; ++kk) {
            float a[4], bv[4];
            #pragma unroll
            for (int i = 0; i < 4; ++i) a[i]  = Qs[kk][ty*4 + i];
            #pragma unroll
            for (int j = 0; j < 4; ++j) bv[j] = Ks[kk][tx*4 + j];
            #pragma unroll
            for (int i = 0; i < 4; ++i)
                #pragma unroll
                for (int j = 0; j < 4; ++j)
                    acc[i][j] += a[i] * bv[j];
        }
        __syncthreads();
    }
    #pragma unroll
    for (int i = 0; i < 4; ++i) {
        int gi = bi0 + ty*4 + i;
        #pragma unroll
        for (int j = 0; j < 4; ++j) {
            int gj = bj0 + tx*4 + j;
            sc[((size_t)bw * WT + gi) * WT + gj] =
                acc[i][j] * SCALE + mask[((size_t)n * WT + gi) * WT + gj];
        }
    }
}

// ---------------- row softmax over 256 (in place) ----------------
__global__ __launch_bounds__(256) void softmax256(float* __restrict__ sc) {
    const int tid = threadIdx.x;
    const size_t base = (size_t)blockIdx.x * WT;
    __shared__ float red[256];
    float x = sc[base + tid];
    red[tid] = x; __syncthreads();
    for (int s = 128; s > 0; s >>= 1) {
        if (tid < s) red[tid] = fmaxf(red[tid], red[tid + s]);
        __syncthreads();
    }
    float m = red[0]; __syncthreads();
    float e = __expf(x - m);
    red[tid] = e; __syncthreads();
    for (int s = 128; s > 0; s >>= 1) {
        if (tid < s) red[tid] += red[tid + s];
        __syncthreads();
    }
    sc[base + tid] = e / red[0];
}

// ---------------- O = P @ Vw, scattered back to image layout ----------------
__global__ __launch_bounds__(256) void win_av(
    const float* __restrict__ sc, const float* __restrict__ v,
    float* __restrict__ out)
{
    const int bw = blockIdx.z;
    const int b = bw >> 6, n = bw & 63;
    const int bi0 = blockIdx.y * 64;   // query rows
    const int bc0 = blockIdx.x * 64;   // channel cols
    const int tid = threadIdx.x;
    const int tx = tid & 15, ty = tid >> 4;

    __shared__ float Ps[16][64];   // [kk][i]
    __shared__ float Vs[16][64];   // [kk][c]
    __shared__ int offV[256];
    if (tid < 256) offV[tid] = tok_off(b, n, tid);
    __syncthreads();

    float acc[4][4] = {};
    for (int j0 = 0; j0 < WT; j0 += 16) {
        #pragma unroll
        for (int l = tid; l < 1024; l += 256) {
            int i = l >> 4, kk = l & 15;
            Ps[kk][i] = sc[((size_t)bw * WT + bi0 + i) * WT + (j0 + kk)];
        }
        #pragma unroll
        for (int l = tid; l < 1024; l += 256) {
            int kk = l >> 6, c = l & 63;
            Vs[kk][c] = v[offV[j0 + kk] + bc0 + c];
        }
        __syncthreads();
        #pragma unroll
        for (int kk = 0; kk < 16; ++kk) {
            float a[4], bv[4];
            #pragma unroll
            for (int i = 0; i < 4; ++i) a[i]  = Ps[kk][ty*4 + i];
            #pragma unroll
            for (int j = 0; j < 4; ++j) bv[j] = Vs[kk][tx*4 + j];
            #pragma unroll
            for (int i = 0; i < 4; ++i)
                #pragma unroll
                for (int j = 0; j < 4; ++j)
                    acc[i][j] += a[i] * bv[j];
        }
        __syncthreads();
    }
    #pragma unroll
    for (int i = 0; i < 4; ++i) {
        int ro = tok_off(b, n, bi0 + ty*4 + i);
        #pragma unroll
        for (int j = 0; j < 4; ++j)
            out[ro + bc0 + tx*4 + j] = acc[i][j];
    }
}

// ---------------- FFN1: H = gelu([src|msg] @ W1), K=256 split ----------------
__global__ __launch_bounds__(256) void ffn1(
    const float* __restrict__ src, const float* __restrict__ msg,
    const float* __restrict__ W1, float* __restrict__ Hh)
{
    __shared__ float As[16][64];
    __shared__ float Bs[16][64];
    const int bm0 = blockIdx.y * 64, bn0 = blockIdx.x * 64;
    const int tid = threadIdx.x;
    const int tx = tid & 15, ty = tid >> 4;
    float acc[4][4] = {};

    for (int k0 = 0; k0 < 2*C_; k0 += 16) {
        const float* A = (k0 < C_) ? src : msg;
        const int kbase = (k0 < C_) ? k0 : (k0 - C_);
        #pragma unroll
        for (int l = tid; l < 1024; l += 256) {
            int r = l >> 4, kk = l & 15;
            As[kk][r] = A[(size_t)(bm0 + r) * C_ + kbase + kk];
        }
        #pragma unroll
        for (int l = tid; l < 1024; l += 256) {
            int kk = l >> 6, cn = l & 63;
            Bs[kk][cn] = W1[(size_t)(k0 + kk) * HID_ + (bn0 + cn)];
        }
        __syncthreads();
        #pragma unroll
        for (int kk = 0; kk < 16; ++kk) {
            float a[4], bv[4];
            #pragma unroll
            for (int i = 0; i < 4; ++i) a[i]  = As[kk][ty*4 + i];
            #pragma unroll
            for (int j = 0; j < 4; ++j) bv[j] = Bs[kk][tx*4 + j];
            #pragma unroll
            for (int i = 0; i < 4; ++i)
                #pragma unroll
                for (int j = 0; j < 4; ++j)
                    acc[i][j] += a[i] * bv[j];
        }
        __syncthreads();
    }
    #pragma unroll
    for (int i = 0; i < 4; ++i)
        #pragma unroll
        for (int j = 0; j < 4; ++j) {
            float x = acc[i][j];
            float gx = 0.5f * x * (1.0f + erff(x * 0.70710678118654752f));
            Hh[(size_t)(bm0 + ty*4 + i) * HID_ + (bn0 + tx*4 + j)] = gx;
        }
}

// ---------------- rowwise LayerNorm over C=128 (+optional residual) ----------------
__global__ __launch_bounds__(128) void ln128(
    const float* __restrict__ x, const float* __restrict__ g,
    const float* __restrict__ bb, const float* __restrict__ res,
    float* __restrict__ y)
{
    const int tid = threadIdx.x;
    const size_t base = (size_t)blockIdx.x * C_;
    __shared__ float red[128];
    float v = x[base + tid];
    red[tid] = v; __syncthreads();
    for (int s = 64; s > 0; s >>= 1) {
        if (tid < s) red[tid] += red[tid + s];
        __syncthreads();
    }
    float mean = red[0] * (1.0f / C_); __syncthreads();
    float d = v - mean;
    red[tid] = d * d; __syncthreads();
    for (int s = 64; s > 0; s >>= 1) {
        if (tid < s) red[tid] += red[tid + s];
        __syncthreads();
    }
    float var = red[0] * (1.0f / C_);
    float o = d * rsqrtf(var + 1e-5f) * g[tid] + bb[tid];
    if (res) o += res[base + tid];
    y[base + tid] = o;
}

// ---------------- launch ----------------
extern "C" void kernel_launch(void* const* d_in, const int* in_sizes, int n_in,
                              void* d_out, int out_size) {
    const float* source = (const float*)d_in[0];
    const float* target = (const float*)d_in[1];
    const float* Wq = (const float*)d_in[2];
    const float* Wk = (const float*)d_in[3];
    const float* Wv = (const float*)d_in[4];
    const float* Wm = (const float*)d_in[5];
    const float* g1 = (const float*)d_in[6];
    const float* b1 = (const float*)d_in[7];
    const float* W1 = (const float*)d_in[8];
    const float* W2 = (const float*)d_in[9];
    const float* g2 = (const float*)d_in[10];
    const float* b2 = (const float*)d_in[11];
    const float* mask = (const float*)d_in[12];
    float* out = (float*)d_out;

    float *q, *k, *v, *sc, *ao, *t1, *msg, *hid;
    cudaGetSymbolAddress((void**)&q,   g_q);
    cudaGetSymbolAddress((void**)&k,   g_k);
    cudaGetSymbolAddress((void**)&v,   g_v);
    cudaGetSymbolAddress((void**)&sc,  g_sc);
    cudaGetSymbolAddress((void**)&ao,  g_ao);
    cudaGetSymbolAddress((void**)&t1,  g_t1);
    cudaGetSymbolAddress((void**)&msg, g_msg);
    cudaGetSymbolAddress((void**)&hid, g_hid);

    // 1. Q/K/V projections
    gemm64<<<dim3(C_/64, MT/64), 256>>>(source, Wq, q, MT, C_, C_);
    gemm64<<<dim3(C_/64, MT/64), 256>>>(target, Wk, k, MT, C_, C_);
    gemm64<<<dim3(C_/64, MT/64), 256>>>(target, Wv, v, MT, C_, C_);
    // 2. windowed scores (shift-gather fused)
    win_scores<<<dim3(WT/64, WT/64, B_*NWIN), 256>>>(q, k, mask, sc);
    // 3. softmax
    softmax256<<<B_*NWIN*WT, 256>>>(sc);
    // 4. attn @ V (scatter-unshift fused)
    win_av<<<dim3(C_/64, WT/64, B_*NWIN), 256>>>(sc, v, ao);
    // 5. message = LN1(attn_out @ Wm)
    gemm64<<<dim3(C_/64, MT/64), 256>>>(ao, Wm, t1, MT, C_, C_);
    ln128<<<MT, 128>>>(t1, g1, b1, nullptr, msg);
    // 6. FFN
    ffn1<<<dim3(HID_/64, MT/64), 256>>>(source, msg, W1, hid);
    gemm64<<<dim3(C_/64, MT/64), 256>>>(hid, W2, t1, MT, C_, HID_);
    // 7. out = source + LN2(ffn)
    ln128<<<MT, 128>>>(t1, g2, b2, source, out);
}

// round 6
// speedup vs baseline: 3.0053x; 3.0053x over previous
#include <cuda_runtime.h>
#include <math.h>

#define B_   2
#define HGT  128
#define WID  128
#define C_   128
#define NWIN 64          // 8x8 windows
#define WT   256         // tokens per window (16x16)
#define LTOK (HGT*WID)   // 16384
#define MT   (B_*LTOK)   // 32768
#define HID_ 1024
#define SCALE 0.08838834764831845f  // 1/sqrt(128)

#define PAD  20          // smem row stride (floats): conflict-free fragment LDS
#define BK   16
#define TSZ  (128*PAD)   // one smem tile buffer (floats)

// ---------------- device scratch ----------------
static __device__ float g_q [MT*C_];
static __device__ float g_k [MT*C_];
static __device__ float g_v [MT*C_];
static __device__ float g_sc[(size_t)B_*NWIN*WT*WT];
static __device__ float g_ao[MT*C_];
static __device__ float g_t1[MT*C_];
static __device__ float g_msg[MT*C_];
static __device__ float g_hid[(size_t)MT*HID_];

__device__ __forceinline__ int tok_off(int b, int n, int i) {
    int wy = n >> 3, wx = n & 7;
    int gh = ((wy << 4) + (i >> 4) + 8) & 127;
    int gw = ((wx << 4) + (i & 15) + 8) & 127;
    return ((b * HGT + gh) * WID + gw) * C_;
}

__device__ __forceinline__ float tf32r(float x) {
    unsigned u; asm("cvt.rna.tf32.f32 %0, %1;" : "=r"(u) : "f"(x));
    return __uint_as_float(u);
}

// ---------------- mma compute: 2 ksteps (k8) over current buffers ----------------
__device__ __forceinline__ void mma_compute(const float* __restrict__ As,
                                            const float* __restrict__ Bs,
                                            float (&acc)[4][4][4],
                                            int wm0, int wn0, int lane)
{
    const int r = lane >> 2, c = lane & 3;
    #pragma unroll
    for (int ks = 0; ks < 2; ++ks) {
        const int k = ks * 8;
        unsigned a[4][4], bf[4][2];
        #pragma unroll
        for (int mt = 0; mt < 4; ++mt) {
            const float* p = As + (wm0 + mt*16 + r)*PAD + k + c;
            a[mt][0] = __float_as_uint(p[0]);
            a[mt][1] = __float_as_uint(p[8*PAD]);
            a[mt][2] = __float_as_uint(p[4]);
            a[mt][3] = __float_as_uint(p[8*PAD + 4]);
        }
        #pragma unroll
        for (int nt = 0; nt < 4; ++nt) {
            const float* p = Bs + (wn0 + nt*8 + r)*PAD + k + c;
            bf[nt][0] = __float_as_uint(p[0]);
            bf[nt][1] = __float_as_uint(p[4]);
        }
        #pragma unroll
        for (int mt = 0; mt < 4; ++mt)
            #pragma unroll
            for (int nt = 0; nt < 4; ++nt)
                asm volatile(
                  "mma.sync.aligned.m16n8k8.row.col.f32.tf32.tf32.f32 "
                  "{%0,%1,%2,%3},{%4,%5,%6,%7},{%8,%9},{%0,%1,%2,%3};"
                  : "+f"(acc[mt][nt][0]), "+f"(acc[mt][nt][1]),
                    "+f"(acc[mt][nt][2]), "+f"(acc[mt][nt][3])
                  : "r"(a[mt][0]), "r"(a[mt][1]), "r"(a[mt][2]), "r"(a[mt][3]),
                    "r"(bf[nt][0]), "r"(bf[nt][1]));
    }
}

// ---------------- loaders / smem stores ----------------
// A-style tile (row-major [128][BK]): thread -> row=tid>>1, kseg=(tid&1)*8
__device__ __forceinline__ void ldA(const float* __restrict__ A, int lda, int k0,
                                    int tid, float4& v0, float4& v1) {
    const float* p = A + (size_t)(tid >> 1) * lda + k0 + (tid & 1) * 8;
    v0 = *(const float4*)p; v1 = *(const float4*)(p + 4);
}
__device__ __forceinline__ void ldA_gather(const float* __restrict__ X, const int* __restrict__ off,
                                           int k0, int tid, float4& v0, float4& v1) {
    const float* p = X + off[tid >> 1] + k0 + (tid & 1) * 8;
    v0 = *(const float4*)p; v1 = *(const float4*)(p + 4);
}
__device__ __forceinline__ void stA(float* __restrict__ S, int tid, float4 v0, float4 v1) {
    float* p = S + (tid >> 1) * PAD + (tid & 1) * 8;
    p[0]=tf32r(v0.x); p[1]=tf32r(v0.y); p[2]=tf32r(v0.z); p[3]=tf32r(v0.w);
    p[4]=tf32r(v1.x); p[5]=tf32r(v1.y); p[6]=tf32r(v1.z); p[7]=tf32r(v1.w);
}
// B transpose tile (gmem [K][N] -> smem [n][k]): scalar path
__device__ __forceinline__ void ldBT(const float* __restrict__ B, int ldb, int k0, int bn0,
                                     int tid, float rb[8]) {
    const int kr = tid >> 5, lane = tid & 31;
    const float* p0 = B + (size_t)(k0 + kr)     * ldb + bn0 + lane;
    const float* p1 = B + (size_t)(k0 + kr + 8) * ldb + bn0 + lane;
    #pragma unroll
    for (int i = 0; i < 4; ++i) { rb[i] = p0[32*i]; rb[4+i] = p1[32*i]; }
}
__device__ __forceinline__ void ldBT_gather(const float* __restrict__ V, const int* __restrict__ off,
                                            int k0, int tid, float rb[8]) {
    const int kr = tid >> 5, lane = tid & 31;
    const float* p0 = V + off[k0 + kr]     + lane;
    const float* p1 = V + off[k0 + kr + 8] + lane;
    #pragma unroll
    for (int i = 0; i < 4; ++i) { rb[i] = p0[32*i]; rb[4+i] = p1[32*i]; }
}
__device__ __forceinline__ void stBT(float* __restrict__ S, int tid, const float rb[8]) {
    const int kr = tid >> 5, lane = tid & 31;
    #pragma unroll
    for (int i = 0; i < 4; ++i) {
        S[(lane + 32*i)*PAD + kr    ] = tf32r(rb[i]);
        S[(lane + 32*i)*PAD + kr + 8] = tf32r(rb[4+i]);
    }
}

// ---------------- plain store ----------------
__device__ __forceinline__ void store_plain(float* __restrict__ Cg, int ldc, int bm0, int bn0,
                                            const float (&acc)[4][4][4], int wm0, int wn0, int lane)
{
    const int r = lane >> 2, q2 = (lane & 3) * 2;
    #pragma unroll
    for (int mt = 0; mt < 4; ++mt) {
        const int row = bm0 + wm0 + mt*16 + r;
        #pragma unroll
        for (int nt = 0; nt < 4; ++nt) {
            const int col = bn0 + wn0 + nt*8 + q2;
            *(float2*)&Cg[(size_t)row * ldc + col]       = make_float2(acc[mt][nt][0], acc[mt][nt][1]);
            *(float2*)&Cg[(size_t)(row + 8) * ldc + col] = make_float2(acc[mt][nt][2], acc[mt][nt][3]);
        }
    }
}

// ---------------- generic GEMM C = A(Mx K) @ B(K x N), tf32 ----------------
__global__ __launch_bounds__(256) void gemm_tf32(
    const float* __restrict__ A, const float* __restrict__ B, float* __restrict__ Cg,
    int N, int K)
{
    __shared__ float As2[2*TSZ], Bs2[2*TSZ];
    const int tid = threadIdx.x, lane = tid & 31, wid = tid >> 5;
    const int wm0 = (wid >> 2) * 64, wn0 = (wid & 3) * 32;
    const int bm0 = blockIdx.y * 128, bn0 = blockIdx.x * 128;
    const float* Ab = A + (size_t)bm0 * K;
    float acc[4][4][4] = {};
    float4 a0, a1; float rb[8];

    ldA(Ab, K, 0, tid, a0, a1); ldBT(B, N, 0, bn0, tid, rb);
    stA(As2, tid, a0, a1); stBT(Bs2, tid, rb);
    __syncthreads();
    int buf = 0;
    for (int k0 = BK; k0 < K; k0 += BK) {
        ldA(Ab, K, k0, tid, a0, a1); ldBT(B, N, k0, bn0, tid, rb);
        mma_compute(As2 + buf*TSZ, Bs2 + buf*TSZ, acc, wm0, wn0, lane);
        stA(As2 + (buf^1)*TSZ, tid, a0, a1); stBT(Bs2 + (buf^1)*TSZ, tid, rb);
        __syncthreads();
        buf ^= 1;
    }
    mma_compute(As2 + buf*TSZ, Bs2 + buf*TSZ, acc, wm0, wn0, lane);
    store_plain(Cg, N, bm0, bn0, acc, wm0, wn0, lane);
}

// ---------------- QKV: z selects (A, W, O) ----------------
__global__ __launch_bounds__(256) void qkv_tf32(
    const float* __restrict__ src, const float* __restrict__ tgt,
    const float* __restrict__ Wq, const float* __restrict__ Wk, const float* __restrict__ Wv)
{
    __shared__ float As2[2*TSZ], Bs2[2*TSZ];
    const int z = blockIdx.z;
    const float* A = (z == 0) ? src : tgt;
    const float* W = (z == 0) ? Wq : (z == 1 ? Wk : Wv);
    float* O = (z == 0) ? g_q : (z == 1 ? g_k : g_v);

    const int tid = threadIdx.x, lane = tid & 31, wid = tid >> 5;
    const int wm0 = (wid >> 2) * 64, wn0 = (wid & 3) * 32;
    const int bm0 = blockIdx.y * 128;
    const float* Ab = A + (size_t)bm0 * C_;
    float acc[4][4][4] = {};
    float4 a0, a1; float rb[8];

    ldA(Ab, C_, 0, tid, a0, a1); ldBT(W, C_, 0, 0, tid, rb);
    stA(As2, tid, a0, a1); stBT(Bs2, tid, rb);
    __syncthreads();
    int buf = 0;
    for (int k0 = BK; k0 < C_; k0 += BK) {
        ldA(Ab, C_, k0, tid, a0, a1); ldBT(W, C_, k0, 0, tid, rb);
        mma_compute(As2 + buf*TSZ, Bs2 + buf*TSZ, acc, wm0, wn0, lane);
        stA(As2 + (buf^1)*TSZ, tid, a0, a1); stBT(Bs2 + (buf^1)*TSZ, tid, rb);
        __syncthreads();
        buf ^= 1;
    }
    mma_compute(As2 + buf*TSZ, Bs2 + buf*TSZ, acc, wm0, wn0, lane);
    store_plain(O, C_, bm0, 0, acc, wm0, wn0, lane);
}

// ---------------- window scores: S = Qw Kw^T * scale + mask ----------------
__global__ __launch_bounds__(256) void win_scores_tf32(const float* __restrict__ mask)
{
    __shared__ float As2[2*TSZ], Bs2[2*TSZ];
    __shared__ int offQ[128], offK[128];
    const int bw = blockIdx.z, b = bw >> 6, n = bw & 63;
    const int bi0 = blockIdx.y * 128, bj0 = blockIdx.x * 128;
    const int tid = threadIdx.x, lane = tid & 31, wid = tid >> 5;
    const int wm0 = (wid >> 2) * 64, wn0 = (wid & 3) * 32;

    if (tid < 128) offQ[tid] = tok_off(b, n, bi0 + tid);
    else           offK[tid - 128] = tok_off(b, n, bj0 + tid - 128);
    __syncthreads();

    float acc[4][4][4] = {};
    float4 a0, a1, b0, b1;
    ldA_gather(g_q, offQ, 0, tid, a0, a1);
    ldA_gather(g_k, offK, 0, tid, b0, b1);
    stA(As2, tid, a0, a1); stA(Bs2, tid, b0, b1);   // B stored [n][k] directly
    __syncthreads();
    int buf = 0;
    for (int k0 = BK; k0 < C_; k0 += BK) {
        ldA_gather(g_q, offQ, k0, tid, a0, a1);
        ldA_gather(g_k, offK, k0, tid, b0, b1);
        mma_compute(As2 + buf*TSZ, Bs2 + buf*TSZ, acc, wm0, wn0, lane);
        stA(As2 + (buf^1)*TSZ, tid, a0, a1); stA(Bs2 + (buf^1)*TSZ, tid, b0, b1);
        __syncthreads();
        buf ^= 1;
    }
    mma_compute(As2 + buf*TSZ, Bs2 + buf*TSZ, acc, wm0, wn0, lane);

    // epilogue: *scale + mask, write fp32 scores
    const int r = lane >> 2, q2 = (lane & 3) * 2;
    #pragma unroll
    for (int mt = 0; mt < 4; ++mt) {
        #pragma unroll
        for (int nt = 0; nt < 4; ++nt) {
            const int col = bj0 + wn0 + nt*8 + q2;
            #pragma unroll
            for (int hh = 0; hh < 2; ++hh) {
                const int row = bi0 + wm0 + mt*16 + r + hh*8;
                const size_t sidx = ((size_t)bw * WT + row) * WT + col;
                const size_t midx = ((size_t)n  * WT + row) * WT + col;
                float2 mk = *(const float2*)&mask[midx];
                float2 o  = make_float2(acc[mt][nt][2*hh]   * SCALE + mk.x,
                                        acc[mt][nt][2*hh+1] * SCALE + mk.y);
                *(float2*)&g_sc[sidx] = o;
            }
        }
    }
}

// ---------------- O = P @ Vw, scatter-unshift on store ----------------
__global__ __launch_bounds__(256) void win_av_tf32()
{
    __shared__ float As2[2*TSZ], Bs2[2*TSZ];
    __shared__ int offV[256];
    const int bw = blockIdx.z, b = bw >> 6, n = bw & 63;
    const int bi0 = blockIdx.y * 128;
    const int tid = threadIdx.x, lane = tid & 31, wid = tid >> 5;
    const int wm0 = (wid >> 2) * 64, wn0 = (wid & 3) * 32;

    offV[tid] = tok_off(b, n, tid);
    __syncthreads();

    const float* P = g_sc + ((size_t)bw * WT + bi0) * WT;  // [128][256]
    float acc[4][4][4] = {};
    float4 a0, a1; float rb[8];
    ldA(P, WT, 0, tid, a0, a1); ldBT_gather(g_v, offV, 0, tid, rb);
    stA(As2, tid, a0, a1); stBT(Bs2, tid, rb);
    __syncthreads();
    int buf = 0;
    for (int k0 = BK; k0 < WT; k0 += BK) {
        ldA(P, WT, k0, tid, a0, a1); ldBT_gather(g_v, offV, k0, tid, rb);
        mma_compute(As2 + buf*TSZ, Bs2 + buf*TSZ, acc, wm0, wn0, lane);
        stA(As2 + (buf^1)*TSZ, tid, a0, a1); stBT(Bs2 + (buf^1)*TSZ, tid, rb);
        __syncthreads();
        buf ^= 1;
    }
    mma_compute(As2 + buf*TSZ, Bs2 + buf*TSZ, acc, wm0, wn0, lane);

    const int r = lane >> 2, q2 = (lane & 3) * 2;
    #pragma unroll
    for (int mt = 0; mt < 4; ++mt) {
        #pragma unroll
        for (int hh = 0; hh < 2; ++hh) {
            const int lrow = wm0 + mt*16 + r + hh*8;           // 0..127 within tile
            const int ro = offV[bi0 + lrow];
            #pragma unroll
            for (int nt = 0; nt < 4; ++nt) {
                const int col = wn0 + nt*8 + q2;
                *(float2*)&g_ao[ro + col] =
                    make_float2(acc[mt][nt][2*hh], acc[mt][nt][2*hh+1]);
            }
        }
    }
}

// ---------------- FFN1: H = gelu([src|msg] @ W1) ----------------
__global__ __launch_bounds__(256) void ffn1_tf32(
    const float* __restrict__ src, const float* __restrict__ W1)
{
    __shared__ float As2[2*TSZ], Bs2[2*TSZ];
    const int tid = threadIdx.x, lane = tid & 31, wid = tid >> 5;
    const int wm0 = (wid >> 2) * 64, wn0 = (wid & 3) * 32;
    const int bm0 = blockIdx.y * 128, bn0 = blockIdx.x * 128;
    const float* A0 = src   + (size_t)bm0 * C_;
    const float* A1 = g_msg + (size_t)bm0 * C_;
    float acc[4][4][4] = {};
    float4 a0, a1; float rb[8];

    ldA(A0, C_, 0, tid, a0, a1); ldBT(W1, HID_, 0, bn0, tid, rb);
    stA(As2, tid, a0, a1); stBT(Bs2, tid, rb);
    __syncthreads();
    int buf = 0;
    for (int k0 = BK; k0 < 2*C_; k0 += BK) {
        const float* Ae = (k0 < C_) ? A0 : A1;
        ldA(Ae, C_, k0 & (C_-1), tid, a0, a1);
        ldBT(W1, HID_, k0, bn0, tid, rb);
        mma_compute(As2 + buf*TSZ, Bs2 + buf*TSZ, acc, wm0, wn0, lane);
        stA(As2 + (buf^1)*TSZ, tid, a0, a1); stBT(Bs2 + (buf^1)*TSZ, tid, rb);
        __syncthreads();
        buf ^= 1;
    }
    mma_compute(As2 + buf*TSZ, Bs2 + buf*TSZ, acc, wm0, wn0, lane);

    const int r = lane >> 2, q2 = (lane & 3) * 2;
    #pragma unroll
    for (int mt = 0; mt < 4; ++mt) {
        #pragma unroll
        for (int nt = 0; nt < 4; ++nt) {
            const int col = bn0 + wn0 + nt*8 + q2;
            #pragma unroll
            for (int hh = 0; hh < 2; ++hh) {
                const int row = bm0 + wm0 + mt*16 + r + hh*8;
                float x0 = acc[mt][nt][2*hh], x1 = acc[mt][nt][2*hh+1];
                float gg0 = 0.5f * x0 * (1.0f + erff(x0 * 0.70710678118654752f));
                float gg1 = 0.5f * x1 * (1.0f + erff(x1 * 0.70710678118654752f));
                *(float2*)&g_hid[(size_t)row * HID_ + col] = make_float2(gg0, gg1);
            }
        }
    }
}

// ---------------- row softmax over 256 (in place) ----------------
__global__ __launch_bounds__(256) void softmax256(float* __restrict__ sc) {
    const int tid = threadIdx.x;
    const size_t base = (size_t)blockIdx.x * WT;
    __shared__ float red[256];
    float x = sc[base + tid];
    red[tid] = x; __syncthreads();
    for (int s = 128; s > 0; s >>= 1) {
        if (tid < s) red[tid] = fmaxf(red[tid], red[tid + s]);
        __syncthreads();
    }
    float m = red[0]; __syncthreads();
    float e = __expf(x - m);
    red[tid] = e; __syncthreads();
    for (int s = 128; s > 0; s >>= 1) {
        if (tid < s) red[tid] += red[tid + s];
        __syncthreads();
    }
    sc[base + tid] = e / red[0];
}

// ---------------- rowwise LayerNorm over C=128 (+optional residual) ----------------
__global__ __launch_bounds__(128) void ln128(
    const float* __restrict__ x, const float* __restrict__ g,
    const float* __restrict__ bb, const float* __restrict__ res,
    float* __restrict__ y)
{
    const int tid = threadIdx.x;
    const size_t base = (size_t)blockIdx.x * C_;
    __shared__ float red[128];
    float v = x[base + tid];
    red[tid] = v; __syncthreads();
    for (int s = 64; s > 0; s >>= 1) {
        if (tid < s) red[tid] += red[tid + s];
        __syncthreads();
    }
    float mean = red[0] * (1.0f / C_); __syncthreads();
    float d = v - mean;
    red[tid] = d * d; __syncthreads();
    for (int s = 64; s > 0; s >>= 1) {
        if (tid < s) red[tid] += red[tid + s];
        __syncthreads();
    }
    float var = red[0] * (1.0f / C_);
    float o = d * rsqrtf(var + 1e-5f) * g[tid] + bb[tid];
    if (res) o += res[base + tid];
    y[base + tid] = o;
}

// ---------------- launch ----------------
extern "C" void kernel_launch(void* const* d_in, const int* in_sizes, int n_in,
                              void* d_out, int out_size) {
    const float* source = (const float*)d_in[0];
    const float* target = (const float*)d_in[1];
    const float* Wq = (const float*)d_in[2];
    const float* Wk = (const float*)d_in[3];
    const float* Wv = (const float*)d_in[4];
    const float* Wm = (const float*)d_in[5];
    const float* g1 = (const float*)d_in[6];
    const float* b1 = (const float*)d_in[7];
    const float* W1 = (const float*)d_in[8];
    const float* W2 = (const float*)d_in[9];
    const float* g2 = (const float*)d_in[10];
    const float* b2 = (const float*)d_in[11];
    const float* mask = (const float*)d_in[12];
    float* out = (float*)d_out;

    float *sc, *ao, *t1, *msg, *hid;
    cudaGetSymbolAddress((void**)&sc,  g_sc);
    cudaGetSymbolAddress((void**)&ao,  g_ao);
    cudaGetSymbolAddress((void**)&t1,  g_t1);
    cudaGetSymbolAddress((void**)&msg, g_msg);
    cudaGetSymbolAddress((void**)&hid, g_hid);

    // 1. Q/K/V projections (tensor core, tf32)
    qkv_tf32<<<dim3(1, MT/128, 3), 256>>>(source, target, Wq, Wk, Wv);
    // 2. window scores (shift-gather fused)
    win_scores_tf32<<<dim3(2, 2, B_*NWIN), 256>>>(mask);
    // 3. softmax
    softmax256<<<B_*NWIN*WT, 256>>>(sc);
    // 4. attn @ V (scatter-unshift fused)
    win_av_tf32<<<dim3(1, 2, B_*NWIN), 256>>>();
    // 5. message = LN1(attn_out @ Wm)
    gemm_tf32<<<dim3(1, MT/128), 256>>>(ao, Wm, t1, C_, C_);
    ln128<<<MT, 128>>>(t1, g1, b1, nullptr, msg);
    // 6. FFN
    ffn1_tf32<<<dim3(HID_/128, MT/128), 256>>>(source, W1);
    gemm_tf32<<<dim3(1, MT/128), 256>>>(hid, W2, t1, C_, HID_);
    // 7. out = source + LN2(ffn)
    ln128<<<MT, 128>>>(t1, g2, b2, source, out);
}